// round 7
// baseline (speedup 1.0000x reference)
#include <cuda_runtime.h>
#include <cuda_bf16.h>

#define NN 10000      // num nodes (dataset-fixed)
#define EE 640000     // num edges
#define DD 128        // feature dim

// ---- scratch (__device__ globals; zero-initialized at load) ----------------
__device__ int   g_degcnt[NN];       // out-degree counts (over row)
__device__ int   g_colcnt[NN];       // in-degree counts (over col)
__device__ int   g_off[NN + 1];      // CSR offsets by col
__device__ int   g_cursor[NN];       // scatter cursors
__device__ int   g_srow[EE];         // row[] sorted by col
__device__ float g_dis[NN];          // (deg+1)^{-1/2}
__device__ float g_msg[NN * DD];     // (x@W) * dis[row], fp32

// NOTE: g_degcnt/g_colcnt must be ZERO on entry. They are zero at module load,
// and k_reduce's tail blocks re-zero them at the end of every call, so each
// graph replay starts from a clean state.

// ---------------------------------------------------------------------------
// K1: histograms over row (degree) and col (CSR counts). ILP-2.
// ---------------------------------------------------------------------------
__global__ void k_hist(const int* __restrict__ row,
                       const int* __restrict__ col, int e, int half) {
    int i = blockIdx.x * blockDim.x + threadIdx.x;
    if (i < half) {
        int r0 = row[i];
        int c0 = col[i];
        int j = i + half;
        if (j < e) {
            int r1 = row[j];
            int c1 = col[j];
            atomicAdd(&g_degcnt[r0], 1);
            atomicAdd(&g_degcnt[r1], 1);
            atomicAdd(&g_colcnt[c0], 1);
            atomicAdd(&g_colcnt[c1], 1);
        } else {
            atomicAdd(&g_degcnt[r0], 1);
            atomicAdd(&g_colcnt[c0], 1);
        }
    }
}

// ---------------------------------------------------------------------------
// K2: single-block exclusive scan of colcnt -> offsets/cursor; dis = rsqrt(deg+1)
// ---------------------------------------------------------------------------
__global__ __launch_bounds__(1024) void k_scan(int n) {
    __shared__ int sums[1024];
    const int t = threadIdx.x;
    const int chunk = (n + 1023) / 1024;
    const int beg = t * chunk;
    const int end = min(beg + chunk, n);

    int s = 0;
    for (int i = beg; i < end; i++) s += g_colcnt[i];
    sums[t] = s;
    __syncthreads();

    for (int off = 1; off < 1024; off <<= 1) {
        int v = (t >= off) ? sums[t - off] : 0;
        __syncthreads();
        sums[t] += v;
        __syncthreads();
    }

    int run = (t == 0) ? 0 : sums[t - 1];
    for (int i = beg; i < end; i++) {
        g_off[i]    = run;
        g_cursor[i] = run;
        run += g_colcnt[i];
    }
    if (end == n && beg <= n) g_off[n] = run;

    for (int i = t; i < n; i += 1024)
        g_dis[i] = rsqrtf((float)(g_degcnt[i] + 1));  // +1 self-loop
}

// ---------------------------------------------------------------------------
// K3: counting-sort scatter. ILP-2.
// ---------------------------------------------------------------------------
__global__ void k_sort(const int* __restrict__ row,
                       const int* __restrict__ col, int e, int half) {
    int i = blockIdx.x * blockDim.x + threadIdx.x;
    if (i < half) {
        int c0 = col[i];
        int r0 = row[i];
        int j = i + half;
        if (j < e) {
            int c1 = col[j];
            int r1 = row[j];
            int p0 = atomicAdd(&g_cursor[c0], 1);
            int p1 = atomicAdd(&g_cursor[c1], 1);
            g_srow[p0] = r0;
            g_srow[p1] = r1;
        } else {
            int p0 = atomicAdd(&g_cursor[c0], 1);
            g_srow[p0] = r0;
        }
    }
}

// ---------------------------------------------------------------------------
// K4: fused GEMM + row scale:  g_msg[i,:] = (x[i,:] @ W) * dis[i]
// 256 threads, 16 rows/block (grid 625 -> 34 warps/SM). W staged chunk-wise
// in smem (32 k x 128 cols = 16KB) so inner-loop W reads are LDS, not LDG.
// Half h = tid>>7 handles rows 8h..8h+7; j = tid&127 is the output column.
// ---------------------------------------------------------------------------
#define RPB 16
#define KCHUNK 32
__global__ __launch_bounds__(256) void k_gemm(const float* __restrict__ x,
                                              const float* __restrict__ W,
                                              int n) {
    __shared__ float4 xs[RPB][DD / 4];        // 8KB  x tile
    __shared__ float  ws[KCHUNK][DD];         // 16KB W chunk
    const int tid = threadIdx.x;
    const int j   = tid & 127;                // output column
    const int h   = tid >> 7;                 // row-half 0/1
    const int r0  = blockIdx.x * RPB;

    // load x tile: 16 rows x 32 float4 = 512 float4; 256 threads -> 2 each
    const float4* x4 = (const float4*)x;
#pragma unroll
    for (int i = 0; i < 2; i++) {
        int idx = tid + i * 256;              // 0..511
        int r = idx >> 5, c = idx & 31;
        int gr = r0 + r;
        xs[r][c] = (gr < n) ? x4[gr * (DD / 4) + c]
                            : make_float4(0.f, 0.f, 0.f, 0.f);
    }

    float acc[RPB / 2];
#pragma unroll
    for (int r = 0; r < RPB / 2; r++) acc[r] = 0.0f;

    const float4* W4 = (const float4*)W;
    for (int c0 = 0; c0 < DD; c0 += KCHUNK) {
        __syncthreads();   // xs ready (first iter) / ws consumers done (later)
        // stage W[c0..c0+32)[:] : 1024 float4; 256 threads -> 4 each
#pragma unroll
        for (int i = 0; i < 4; i++) {
            int idx = tid + i * 256;          // 0..1023 ; kk = idx>>5, c4 = idx&31
            ((float4*)ws)[idx] = W4[(c0 + (idx >> 5)) * (DD / 4) + (idx & 31)];
        }
        __syncthreads();

#pragma unroll
        for (int kk = 0; kk < KCHUNK; kk += 4) {
            float w0 = ws[kk + 0][j];
            float w1 = ws[kk + 1][j];
            float w2 = ws[kk + 2][j];
            float w3 = ws[kk + 3][j];
#pragma unroll
            for (int r = 0; r < RPB / 2; r++) {
                float4 xv = xs[h * 8 + r][(c0 + kk) >> 2];
                acc[r] = fmaf(xv.x, w0, acc[r]);
                acc[r] = fmaf(xv.y, w1, acc[r]);
                acc[r] = fmaf(xv.z, w2, acc[r]);
                acc[r] = fmaf(xv.w, w3, acc[r]);
            }
        }
    }

#pragma unroll
    for (int r = 0; r < RPB / 2; r++) {
        int gr = r0 + h * 8 + r;
        if (gr < n) g_msg[gr * DD + j] = acc[r] * g_dis[gr];
    }
}

// ---------------------------------------------------------------------------
// K5: gather-reduce + finalize (round-2 version: unroll 4, fp32), plus tail
// blocks that zero the histogram counters for the next call.
// ---------------------------------------------------------------------------
#define NODE_BLOCKS ((NN + 7) / 8)
#define ZERO_BLOCKS 8
__global__ __launch_bounds__(256) void k_reduce(float* __restrict__ out,
                                                const float* __restrict__ bias,
                                                int n) {
    if (blockIdx.x >= NODE_BLOCKS) {
        int t = (blockIdx.x - NODE_BLOCKS) * 256 + threadIdx.x;
        int stride = ZERO_BLOCKS * 256;
        for (int i = t; i < NN; i += stride) {
            g_degcnt[i] = 0;
            g_colcnt[i] = 0;
        }
        return;
    }

    const int node = blockIdx.x * 8 + (threadIdx.x >> 5);
    const int lane = threadIdx.x & 31;
    if (node >= n) return;

    const float4* msg4 = (const float4*)g_msg;   // row stride = 32 float4
    const int beg = g_off[node];
    const int end = g_off[node + 1];

    float4 acc = msg4[node * 32 + lane];          // self-loop term
    int e = beg;
    for (; e + 4 <= end; e += 4) {
        int r0 = g_srow[e + 0];
        int r1 = g_srow[e + 1];
        int r2 = g_srow[e + 2];
        int r3 = g_srow[e + 3];
        float4 v0 = msg4[r0 * 32 + lane];
        float4 v1 = msg4[r1 * 32 + lane];
        float4 v2 = msg4[r2 * 32 + lane];
        float4 v3 = msg4[r3 * 32 + lane];
        acc.x += (v0.x + v1.x) + (v2.x + v3.x);
        acc.y += (v0.y + v1.y) + (v2.y + v3.y);
        acc.z += (v0.z + v1.z) + (v2.z + v3.z);
        acc.w += (v0.w + v1.w) + (v2.w + v3.w);
    }
    for (; e < end; e++) {
        float4 v = msg4[g_srow[e] * 32 + lane];
        acc.x += v.x; acc.y += v.y; acc.z += v.z; acc.w += v.w;
    }

    const float s = g_dis[node];
    const float4 b = ((const float4*)bias)[lane];
    float4 o;
    o.x = fmaf(s, acc.x, b.x);
    o.y = fmaf(s, acc.y, b.y);
    o.z = fmaf(s, acc.z, b.z);
    o.w = fmaf(s, acc.w, b.w);
    ((float4*)out)[node * 32 + lane] = o;
}

// ---------------------------------------------------------------------------
extern "C" void kernel_launch(void* const* d_in, const int* in_sizes, int n_in,
                              void* d_out, int out_size) {
    const float* x    = (const float*)d_in[0];
    const int*   ei   = (const int*)d_in[1];
    const float* W    = (const float*)d_in[2];
    const float* bias = (const float*)d_in[3];
    float* out = (float*)d_out;

    const int n = in_sizes[0] / DD;   // 10000
    const int e = in_sizes[1] / 2;    // 640000
    const int half = (e + 1) / 2;

    const int* row = ei;              // edge_index[0]
    const int* col = ei + e;          // edge_index[1]

    k_hist<<<(half + 255) / 256, 256>>>(row, col, e, half);
    k_scan<<<1, 1024>>>(n);
    k_sort<<<(half + 255) / 256, 256>>>(row, col, e, half);
    k_gemm<<<(n + RPB - 1) / RPB, 256>>>(x, W, n);
    k_reduce<<<NODE_BLOCKS + ZERO_BLOCKS, 256>>>(out, bias, n);
}

// round 8
// speedup vs baseline: 1.0407x; 1.0407x over previous
#include <cuda_runtime.h>
#include <cuda_bf16.h>

#define NN 10000      // num nodes (dataset-fixed)
#define EE 640000     // num edges
#define DD 128        // feature dim

// ---- scratch (__device__ globals; zero-initialized at load) ----------------
__device__ int   g_degcnt[NN];       // out-degree counts (over row)
__device__ int   g_colcnt[NN];       // in-degree counts (over col)
__device__ int   g_off[NN + 1];      // CSR offsets by col
__device__ int   g_cursor[NN];       // scatter cursors
__device__ int   g_srow[EE];         // row[] sorted by col
__device__ float g_dis[NN];          // (deg+1)^{-1/2}
__device__ float g_msg[NN * DD];     // (x@W) * dis[row], fp32

// NOTE: g_degcnt/g_colcnt must be ZERO on entry. They are zero at module load,
// and k_reduce's tail blocks re-zero them at the end of every call.

// ---------------------------------------------------------------------------
// K1: histograms over row (degree) and col (CSR counts). ILP-2.
// ---------------------------------------------------------------------------
__global__ void k_hist(const int* __restrict__ row,
                       const int* __restrict__ col, int e, int half) {
    int i = blockIdx.x * blockDim.x + threadIdx.x;
    if (i < half) {
        int r0 = row[i];
        int c0 = col[i];
        int j = i + half;
        if (j < e) {
            int r1 = row[j];
            int c1 = col[j];
            atomicAdd(&g_degcnt[r0], 1);
            atomicAdd(&g_degcnt[r1], 1);
            atomicAdd(&g_colcnt[c0], 1);
            atomicAdd(&g_colcnt[c1], 1);
        } else {
            atomicAdd(&g_degcnt[r0], 1);
            atomicAdd(&g_colcnt[c0], 1);
        }
    }
}

// ---------------------------------------------------------------------------
// K2: single-block exclusive scan of colcnt -> offsets/cursor; dis = rsqrt(deg+1)
// ---------------------------------------------------------------------------
__global__ __launch_bounds__(1024) void k_scan(int n) {
    __shared__ int sums[1024];
    const int t = threadIdx.x;
    const int chunk = (n + 1023) / 1024;
    const int beg = t * chunk;
    const int end = min(beg + chunk, n);

    int s = 0;
    for (int i = beg; i < end; i++) s += g_colcnt[i];
    sums[t] = s;
    __syncthreads();

    for (int off = 1; off < 1024; off <<= 1) {
        int v = (t >= off) ? sums[t - off] : 0;
        __syncthreads();
        sums[t] += v;
        __syncthreads();
    }

    int run = (t == 0) ? 0 : sums[t - 1];
    for (int i = beg; i < end; i++) {
        g_off[i]    = run;
        g_cursor[i] = run;
        run += g_colcnt[i];
    }
    if (end == n && beg <= n) g_off[n] = run;

    for (int i = t; i < n; i += 1024)
        g_dis[i] = rsqrtf((float)(g_degcnt[i] + 1));  // +1 self-loop
}

// ---------------------------------------------------------------------------
// K3: counting-sort scatter. ILP-2.
// ---------------------------------------------------------------------------
__global__ void k_sort(const int* __restrict__ row,
                       const int* __restrict__ col, int e, int half) {
    int i = blockIdx.x * blockDim.x + threadIdx.x;
    if (i < half) {
        int c0 = col[i];
        int r0 = row[i];
        int j = i + half;
        if (j < e) {
            int c1 = col[j];
            int r1 = row[j];
            int p0 = atomicAdd(&g_cursor[c0], 1);
            int p1 = atomicAdd(&g_cursor[c1], 1);
            g_srow[p0] = r0;
            g_srow[p1] = r1;
        } else {
            int p0 = atomicAdd(&g_cursor[c0], 1);
            g_srow[p0] = r0;
        }
    }
}

// ---------------------------------------------------------------------------
// K4: register-tiled SGEMM + row scale:  g_msg[i,:] = (x[i,:] @ W) * dis[i]
// Block 256 thr = 8 row-groups x 32 col-groups; thread tile 4x4 outputs.
// Per k: 1 broadcast LDS.128 (x) + 1 conflict-free LDS.128 (W) per 16 FMA.
// ---------------------------------------------------------------------------
#define TM 32      // rows per block
#define KC 32      // k chunk
__global__ __launch_bounds__(256) void k_gemm(const float* __restrict__ x,
                                              const float* __restrict__ W,
                                              int n) {
    __shared__ float xs[KC][36];     // x chunk, transposed [k][row], padded
    __shared__ float ws[KC][DD];     // W chunk [k][col]
    const int tid = threadIdx.x;
    const int tx  = tid & 31;        // col group: cols tx*4 .. tx*4+3
    const int ty  = tid >> 5;        // row group: rows ty*4 .. ty*4+3
    const int r0  = blockIdx.x * TM;

    float acc[4][4];
#pragma unroll
    for (int r = 0; r < 4; r++)
#pragma unroll
        for (int c = 0; c < 4; c++) acc[r][c] = 0.0f;

    const float4* W4 = (const float4*)W;

    for (int c0 = 0; c0 < DD; c0 += KC) {
        __syncthreads();
        // stage x chunk transposed: 32 rows x 32 k (1 float4 per thread)
        {
            int row = tid >> 3;           // 0..31
            int k4  = (tid & 7) * 4;      // 0,4,...,28
            int gr = r0 + row;
            float4 v = (gr < n) ? *(const float4*)&x[gr * DD + c0 + k4]
                                : make_float4(0.f, 0.f, 0.f, 0.f);
            xs[k4 + 0][row] = v.x;
            xs[k4 + 1][row] = v.y;
            xs[k4 + 2][row] = v.z;
            xs[k4 + 3][row] = v.w;
        }
        // stage W chunk: 32 k x 128 cols = 1024 float4 (4 per thread)
#pragma unroll
        for (int i = 0; i < 4; i++) {
            int idx = tid + i * 256;      // 0..1023
            int kk = idx >> 5, j4 = idx & 31;
            *(float4*)&ws[kk][j4 * 4] = W4[(c0 + kk) * (DD / 4) + j4];
        }
        __syncthreads();

#pragma unroll 8
        for (int kk = 0; kk < KC; kk++) {
            float4 xv = *(const float4*)&xs[kk][ty * 4];
            float4 wv = *(const float4*)&ws[kk][tx * 4];
            float xr[4] = {xv.x, xv.y, xv.z, xv.w};
            float wc[4] = {wv.x, wv.y, wv.z, wv.w};
#pragma unroll
            for (int r = 0; r < 4; r++)
#pragma unroll
                for (int c = 0; c < 4; c++)
                    acc[r][c] = fmaf(xr[r], wc[c], acc[r][c]);
        }
    }

#pragma unroll
    for (int r = 0; r < 4; r++) {
        int gr = r0 + ty * 4 + r;
        if (gr < n) {
            float s = g_dis[gr];
            float4 o = make_float4(acc[r][0] * s, acc[r][1] * s,
                                   acc[r][2] * s, acc[r][3] * s);
            *(float4*)&g_msg[gr * DD + tx * 4] = o;
        }
    }
}

// ---------------------------------------------------------------------------
// K5: gather-reduce + finalize (round-2 version: unroll 4, fp32), plus tail
// blocks that zero the histogram counters for the next call.
// ---------------------------------------------------------------------------
#define NODE_BLOCKS ((NN + 7) / 8)
#define ZERO_BLOCKS 8
__global__ __launch_bounds__(256) void k_reduce(float* __restrict__ out,
                                                const float* __restrict__ bias,
                                                int n) {
    if (blockIdx.x >= NODE_BLOCKS) {
        int t = (blockIdx.x - NODE_BLOCKS) * 256 + threadIdx.x;
        int stride = ZERO_BLOCKS * 256;
        for (int i = t; i < NN; i += stride) {
            g_degcnt[i] = 0;
            g_colcnt[i] = 0;
        }
        return;
    }

    const int node = blockIdx.x * 8 + (threadIdx.x >> 5);
    const int lane = threadIdx.x & 31;
    if (node >= n) return;

    const float4* msg4 = (const float4*)g_msg;   // row stride = 32 float4
    const int beg = g_off[node];
    const int end = g_off[node + 1];

    float4 acc = msg4[node * 32 + lane];          // self-loop term
    int e = beg;
    for (; e + 4 <= end; e += 4) {
        int r0 = g_srow[e + 0];
        int r1 = g_srow[e + 1];
        int r2 = g_srow[e + 2];
        int r3 = g_srow[e + 3];
        float4 v0 = msg4[r0 * 32 + lane];
        float4 v1 = msg4[r1 * 32 + lane];
        float4 v2 = msg4[r2 * 32 + lane];
        float4 v3 = msg4[r3 * 32 + lane];
        acc.x += (v0.x + v1.x) + (v2.x + v3.x);
        acc.y += (v0.y + v1.y) + (v2.y + v3.y);
        acc.z += (v0.z + v1.z) + (v2.z + v3.z);
        acc.w += (v0.w + v1.w) + (v2.w + v3.w);
    }
    for (; e < end; e++) {
        float4 v = msg4[g_srow[e] * 32 + lane];
        acc.x += v.x; acc.y += v.y; acc.z += v.z; acc.w += v.w;
    }

    const float s = g_dis[node];
    const float4 b = ((const float4*)bias)[lane];
    float4 o;
    o.x = fmaf(s, acc.x, b.x);
    o.y = fmaf(s, acc.y, b.y);
    o.z = fmaf(s, acc.z, b.z);
    o.w = fmaf(s, acc.w, b.w);
    ((float4*)out)[node * 32 + lane] = o;
}

// ---------------------------------------------------------------------------
extern "C" void kernel_launch(void* const* d_in, const int* in_sizes, int n_in,
                              void* d_out, int out_size) {
    const float* x    = (const float*)d_in[0];
    const int*   ei   = (const int*)d_in[1];
    const float* W    = (const float*)d_in[2];
    const float* bias = (const float*)d_in[3];
    float* out = (float*)d_out;

    const int n = in_sizes[0] / DD;   // 10000
    const int e = in_sizes[1] / 2;    // 640000
    const int half = (e + 1) / 2;

    const int* row = ei;              // edge_index[0]
    const int* col = ei + e;          // edge_index[1]

    k_hist<<<(half + 255) / 256, 256>>>(row, col, e, half);
    k_scan<<<1, 1024>>>(n);
    k_sort<<<(half + 255) / 256, 256>>>(row, col, e, half);
    k_gemm<<<(n + TM - 1) / TM, 256>>>(x, W, n);
    k_reduce<<<NODE_BLOCKS + ZERO_BLOCKS, 256>>>(out, bias, n);
}

// round 9
// speedup vs baseline: 1.1079x; 1.0646x over previous
#include <cuda_runtime.h>
#include <cuda_bf16.h>

#define NN 10000      // num nodes (dataset-fixed)
#define EE 640000     // num edges
#define DD 128        // feature dim

// ---- scratch (__device__ globals; zero-initialized at load) ----------------
__device__ int   g_degcnt[NN];       // out-degree counts (over row)
__device__ int   g_colcnt[NN];       // in-degree counts (over col)
__device__ int   g_off[NN + 1];      // CSR offsets by col
__device__ int   g_cursor[NN];       // scatter cursors
__device__ int   g_srow[EE];         // row[] sorted by col
__device__ float g_dis[NN];          // (deg+1)^{-1/2}
__device__ float g_msg[NN * DD];     // h = x@W (UNSCALED), fp32

// NOTE: g_degcnt/g_colcnt must be ZERO on entry. They are zero at module load,
// and k_reduce's tail blocks re-zero them at the end of every call.

// ---------------------------------------------------------------------------
// K1: histograms over row (degree) and col (CSR counts). ILP-2.
// ---------------------------------------------------------------------------
__global__ void k_hist(const int* __restrict__ row,
                       const int* __restrict__ col, int e, int half) {
    int i = blockIdx.x * blockDim.x + threadIdx.x;
    if (i < half) {
        int r0 = row[i];
        int c0 = col[i];
        int j = i + half;
        if (j < e) {
            int r1 = row[j];
            int c1 = col[j];
            atomicAdd(&g_degcnt[r0], 1);
            atomicAdd(&g_degcnt[r1], 1);
            atomicAdd(&g_colcnt[c0], 1);
            atomicAdd(&g_colcnt[c1], 1);
        } else {
            atomicAdd(&g_degcnt[r0], 1);
            atomicAdd(&g_colcnt[c0], 1);
        }
    }
}

// ---------------------------------------------------------------------------
// K2: single-block exclusive scan of colcnt -> offsets/cursor; dis = rsqrt(deg+1)
// ---------------------------------------------------------------------------
__global__ __launch_bounds__(1024) void k_scan(int n) {
    __shared__ int sums[1024];
    const int t = threadIdx.x;
    const int chunk = (n + 1023) / 1024;
    const int beg = t * chunk;
    const int end = min(beg + chunk, n);

    int s = 0;
    for (int i = beg; i < end; i++) s += g_colcnt[i];
    sums[t] = s;
    __syncthreads();

    for (int off = 1; off < 1024; off <<= 1) {
        int v = (t >= off) ? sums[t - off] : 0;
        __syncthreads();
        sums[t] += v;
        __syncthreads();
    }

    int run = (t == 0) ? 0 : sums[t - 1];
    for (int i = beg; i < end; i++) {
        g_off[i]    = run;
        g_cursor[i] = run;
        run += g_colcnt[i];
    }
    if (end == n && beg <= n) g_off[n] = run;

    for (int i = t; i < n; i += 1024)
        g_dis[i] = rsqrtf((float)(g_degcnt[i] + 1));  // +1 self-loop
}

// ---------------------------------------------------------------------------
// K3: counting-sort scatter. ILP-2.
// ---------------------------------------------------------------------------
__global__ void k_sort(const int* __restrict__ row,
                       const int* __restrict__ col, int e, int half) {
    int i = blockIdx.x * blockDim.x + threadIdx.x;
    if (i < half) {
        int c0 = col[i];
        int r0 = row[i];
        int j = i + half;
        if (j < e) {
            int c1 = col[j];
            int r1 = row[j];
            int p0 = atomicAdd(&g_cursor[c0], 1);
            int p1 = atomicAdd(&g_cursor[c1], 1);
            g_srow[p0] = r0;
            g_srow[p1] = r1;
        } else {
            int p0 = atomicAdd(&g_cursor[c0], 1);
            g_srow[p0] = r0;
        }
    }
}

// ---------------------------------------------------------------------------
// K4: register-tiled SGEMM (UNSCALED):  g_msg[i,:] = x[i,:] @ W
// No dependency on g_dis -> runs concurrently with hist/scan/sort.
// Block 256 thr; thread tile 4x4; per k: 2 LDS.128 per 16 FMA.
// ---------------------------------------------------------------------------
#define TM 32      // rows per block
#define KC 32      // k chunk
__global__ __launch_bounds__(256) void k_gemm(const float* __restrict__ x,
                                              const float* __restrict__ W,
                                              int n) {
    __shared__ float xs[KC][36];     // x chunk, transposed [k][row], padded
    __shared__ float ws[KC][DD];     // W chunk [k][col]
    const int tid = threadIdx.x;
    const int tx  = tid & 31;        // col group: cols tx*4 .. tx*4+3
    const int ty  = tid >> 5;        // row group: rows ty*4 .. ty*4+3
    const int r0  = blockIdx.x * TM;

    float acc[4][4];
#pragma unroll
    for (int r = 0; r < 4; r++)
#pragma unroll
        for (int c = 0; c < 4; c++) acc[r][c] = 0.0f;

    const float4* W4 = (const float4*)W;

    for (int c0 = 0; c0 < DD; c0 += KC) {
        __syncthreads();
        // stage x chunk transposed: 32 rows x 32 k (1 float4 per thread)
        {
            int row = tid >> 3;           // 0..31
            int k4  = (tid & 7) * 4;      // 0,4,...,28
            int gr = r0 + row;
            float4 v = (gr < n) ? *(const float4*)&x[gr * DD + c0 + k4]
                                : make_float4(0.f, 0.f, 0.f, 0.f);
            xs[k4 + 0][row] = v.x;
            xs[k4 + 1][row] = v.y;
            xs[k4 + 2][row] = v.z;
            xs[k4 + 3][row] = v.w;
        }
        // stage W chunk: 32 k x 128 cols = 1024 float4 (4 per thread)
#pragma unroll
        for (int i = 0; i < 4; i++) {
            int idx = tid + i * 256;      // 0..1023
            int kk = idx >> 5, j4 = idx & 31;
            *(float4*)&ws[kk][j4 * 4] = W4[(c0 + kk) * (DD / 4) + j4];
        }
        __syncthreads();

#pragma unroll 8
        for (int kk = 0; kk < KC; kk++) {
            float4 xv = *(const float4*)&xs[kk][ty * 4];
            float4 wv = *(const float4*)&ws[kk][tx * 4];
            float xr[4] = {xv.x, xv.y, xv.z, xv.w};
            float wc[4] = {wv.x, wv.y, wv.z, wv.w};
#pragma unroll
            for (int r = 0; r < 4; r++)
#pragma unroll
                for (int c = 0; c < 4; c++)
                    acc[r][c] = fmaf(xr[r], wc[c], acc[r][c]);
        }
    }

#pragma unroll
    for (int r = 0; r < 4; r++) {
        int gr = r0 + ty * 4 + r;
        if (gr < n) {
            float4 o = make_float4(acc[r][0], acc[r][1], acc[r][2], acc[r][3]);
            *(float4*)&g_msg[gr * DD + tx * 4] = o;
        }
    }
}

// ---------------------------------------------------------------------------
// K5: gather-reduce + finalize. msg is UNSCALED h; apply dis[r] per edge:
// out[i,:] = dis[i]*( sum_e dis[srow[e]]*h[srow[e],:] + dis[i]*h[i,:] ) + bias
// Tail blocks zero the histogram counters for the next call.
// ---------------------------------------------------------------------------
#define NODE_BLOCKS ((NN + 7) / 8)
#define ZERO_BLOCKS 8
__global__ __launch_bounds__(256) void k_reduce(float* __restrict__ out,
                                                const float* __restrict__ bias,
                                                int n) {
    if (blockIdx.x >= NODE_BLOCKS) {
        int t = (blockIdx.x - NODE_BLOCKS) * 256 + threadIdx.x;
        int stride = ZERO_BLOCKS * 256;
        for (int i = t; i < NN; i += stride) {
            g_degcnt[i] = 0;
            g_colcnt[i] = 0;
        }
        return;
    }

    const int node = blockIdx.x * 8 + (threadIdx.x >> 5);
    const int lane = threadIdx.x & 31;
    if (node >= n) return;

    const float4* msg4 = (const float4*)g_msg;   // row stride = 32 float4
    const int beg = g_off[node];
    const int end = g_off[node + 1];
    const float s = g_dis[node];

    float4 hv = msg4[node * 32 + lane];           // self-loop term: dis[i]*h[i]
    float4 acc = make_float4(s * hv.x, s * hv.y, s * hv.z, s * hv.w);

    int e = beg;
    for (; e + 4 <= end; e += 4) {
        int r0 = g_srow[e + 0];
        int r1 = g_srow[e + 1];
        int r2 = g_srow[e + 2];
        int r3 = g_srow[e + 3];
        float d0 = g_dis[r0];
        float d1 = g_dis[r1];
        float d2 = g_dis[r2];
        float d3 = g_dis[r3];
        float4 v0 = msg4[r0 * 32 + lane];
        float4 v1 = msg4[r1 * 32 + lane];
        float4 v2 = msg4[r2 * 32 + lane];
        float4 v3 = msg4[r3 * 32 + lane];
        acc.x = fmaf(d0, v0.x, fmaf(d1, v1.x, fmaf(d2, v2.x, fmaf(d3, v3.x, acc.x))));
        acc.y = fmaf(d0, v0.y, fmaf(d1, v1.y, fmaf(d2, v2.y, fmaf(d3, v3.y, acc.y))));
        acc.z = fmaf(d0, v0.z, fmaf(d1, v1.z, fmaf(d2, v2.z, fmaf(d3, v3.z, acc.z))));
        acc.w = fmaf(d0, v0.w, fmaf(d1, v1.w, fmaf(d2, v2.w, fmaf(d3, v3.w, acc.w))));
    }
    for (; e < end; e++) {
        int r = g_srow[e];
        float d = g_dis[r];
        float4 v = msg4[r * 32 + lane];
        acc.x = fmaf(d, v.x, acc.x);
        acc.y = fmaf(d, v.y, acc.y);
        acc.z = fmaf(d, v.z, acc.z);
        acc.w = fmaf(d, v.w, acc.w);
    }

    const float4 b = ((const float4*)bias)[lane];
    float4 o;
    o.x = fmaf(s, acc.x, b.x);
    o.y = fmaf(s, acc.y, b.y);
    o.z = fmaf(s, acc.z, b.z);
    o.w = fmaf(s, acc.w, b.w);
    ((float4*)out)[node * 32 + lane] = o;
}

// ---------------------------------------------------------------------------
// Launch: fork GEMM to a side stream (no dependency on the CSR chain),
// join before the reduce. Event fork/join is graph-capturable.
// ---------------------------------------------------------------------------
extern "C" void kernel_launch(void* const* d_in, const int* in_sizes, int n_in,
                              void* d_out, int out_size) {
    const float* x    = (const float*)d_in[0];
    const int*   ei   = (const int*)d_in[1];
    const float* W    = (const float*)d_in[2];
    const float* bias = (const float*)d_in[3];
    float* out = (float*)d_out;

    const int n = in_sizes[0] / DD;   // 10000
    const int e = in_sizes[1] / 2;    // 640000
    const int half = (e + 1) / 2;

    const int* row = ei;              // edge_index[0]
    const int* col = ei + e;          // edge_index[1]

    cudaStream_t s1;
    cudaEvent_t evFork, evJoin;
    cudaStreamCreateWithFlags(&s1, cudaStreamNonBlocking);
    cudaEventCreateWithFlags(&evFork, cudaEventDisableTiming);
    cudaEventCreateWithFlags(&evJoin, cudaEventDisableTiming);

    // fork: gemm on s1, CSR chain on the main (capture) stream
    cudaEventRecord(evFork, 0);
    cudaStreamWaitEvent(s1, evFork, 0);
    k_gemm<<<(n + TM - 1) / TM, 256, 0, s1>>>(x, W, n);
    cudaEventRecord(evJoin, s1);

    k_hist<<<(half + 255) / 256, 256>>>(row, col, e, half);
    k_scan<<<1, 1024>>>(n);
    k_sort<<<(half + 255) / 256, 256>>>(row, col, e, half);

    // join: reduce needs both g_msg (s1) and the CSR arrays (main stream)
    cudaStreamWaitEvent(0, evJoin, 0);
    k_reduce<<<NODE_BLOCKS + ZERO_BLOCKS, 256>>>(out, bias, n);
}

// round 11
// speedup vs baseline: 1.2209x; 1.1020x over previous
#include <cuda_runtime.h>
#include <cuda_fp16.h>
#include <cuda_bf16.h>

#define NN 10000      // num nodes (dataset-fixed)
#define EE 640000     // num edges
#define DD 128        // feature dim

// ---- scratch (__device__ globals; zero-initialized at load) ----------------
__device__ int   g_degcnt[NN];       // out-degree counts (over row)
__device__ int   g_colcnt[NN];       // in-degree counts (over col)
__device__ int   g_off[NN + 1];      // CSR offsets by col
__device__ int   g_cursor[NN];       // scatter cursors
__device__ int   g_srow[EE];         // row[] sorted by col
__device__ float g_dis[NN];          // (deg+1)^{-1/2}
__device__ __align__(16) __half g_msg[NN * DD];  // h = x@W, fp16 (scaled in-place by k_scale)

// NOTE: g_degcnt/g_colcnt must be ZERO on entry. They are zero at module load,
// and k_reduce's tail blocks re-zero them at the end of every call.

// ---------------------------------------------------------------------------
// K1: histograms over row (degree) and col (CSR counts). ILP-2.
// ---------------------------------------------------------------------------
__global__ void k_hist(const int* __restrict__ row,
                       const int* __restrict__ col, int e, int half) {
    int i = blockIdx.x * blockDim.x + threadIdx.x;
    if (i < half) {
        int r0 = row[i];
        int c0 = col[i];
        int j = i + half;
        if (j < e) {
            int r1 = row[j];
            int c1 = col[j];
            atomicAdd(&g_degcnt[r0], 1);
            atomicAdd(&g_degcnt[r1], 1);
            atomicAdd(&g_colcnt[c0], 1);
            atomicAdd(&g_colcnt[c1], 1);
        } else {
            atomicAdd(&g_degcnt[r0], 1);
            atomicAdd(&g_colcnt[c0], 1);
        }
    }
}

// ---------------------------------------------------------------------------
// K2: single-block exclusive scan of colcnt -> offsets/cursor; dis = rsqrt(deg+1)
// ---------------------------------------------------------------------------
__global__ __launch_bounds__(1024) void k_scan(int n) {
    __shared__ int sums[1024];
    const int t = threadIdx.x;
    const int chunk = (n + 1023) / 1024;
    const int beg = t * chunk;
    const int end = min(beg + chunk, n);

    int s = 0;
    for (int i = beg; i < end; i++) s += g_colcnt[i];
    sums[t] = s;
    __syncthreads();

    for (int off = 1; off < 1024; off <<= 1) {
        int v = (t >= off) ? sums[t - off] : 0;
        __syncthreads();
        sums[t] += v;
        __syncthreads();
    }

    int run = (t == 0) ? 0 : sums[t - 1];
    for (int i = beg; i < end; i++) {
        g_off[i]    = run;
        g_cursor[i] = run;
        run += g_colcnt[i];
    }
    if (end == n && beg <= n) g_off[n] = run;

    for (int i = t; i < n; i += 1024)
        g_dis[i] = rsqrtf((float)(g_degcnt[i] + 1));  // +1 self-loop
}

// ---------------------------------------------------------------------------
// K3: counting-sort scatter. ILP-2.
// ---------------------------------------------------------------------------
__global__ void k_sort(const int* __restrict__ row,
                       const int* __restrict__ col, int e, int half) {
    int i = blockIdx.x * blockDim.x + threadIdx.x;
    if (i < half) {
        int c0 = col[i];
        int r0 = row[i];
        int j = i + half;
        if (j < e) {
            int c1 = col[j];
            int r1 = row[j];
            int p0 = atomicAdd(&g_cursor[c0], 1);
            int p1 = atomicAdd(&g_cursor[c1], 1);
            g_srow[p0] = r0;
            g_srow[p1] = r1;
        } else {
            int p0 = atomicAdd(&g_cursor[c0], 1);
            g_srow[p0] = r0;
        }
    }
}

// ---------------------------------------------------------------------------
// K4: register-tiled SGEMM (UNSCALED, fp16 out):  g_msg[i,:] = half(x[i,:] @ W)
// No dependency on g_dis -> runs concurrently with hist/scan/sort.
// ---------------------------------------------------------------------------
#define TM 32      // rows per block
#define KC 32      // k chunk
__global__ __launch_bounds__(256) void k_gemm(const float* __restrict__ x,
                                              const float* __restrict__ W,
                                              int n) {
    __shared__ float xs[KC][36];     // x chunk, transposed [k][row], padded
    __shared__ float ws[KC][DD];     // W chunk [k][col]
    const int tid = threadIdx.x;
    const int tx  = tid & 31;        // col group: cols tx*4 .. tx*4+3
    const int ty  = tid >> 5;        // row group: rows ty*4 .. ty*4+3
    const int r0  = blockIdx.x * TM;

    float acc[4][4];
#pragma unroll
    for (int r = 0; r < 4; r++)
#pragma unroll
        for (int c = 0; c < 4; c++) acc[r][c] = 0.0f;

    const float4* W4 = (const float4*)W;

    for (int c0 = 0; c0 < DD; c0 += KC) {
        __syncthreads();
        {
            int row = tid >> 3;           // 0..31
            int k4  = (tid & 7) * 4;      // 0,4,...,28
            int gr = r0 + row;
            float4 v = (gr < n) ? *(const float4*)&x[gr * DD + c0 + k4]
                                : make_float4(0.f, 0.f, 0.f, 0.f);
            xs[k4 + 0][row] = v.x;
            xs[k4 + 1][row] = v.y;
            xs[k4 + 2][row] = v.z;
            xs[k4 + 3][row] = v.w;
        }
#pragma unroll
        for (int i = 0; i < 4; i++) {
            int idx = tid + i * 256;      // 0..1023
            int kk = idx >> 5, j4 = idx & 31;
            *(float4*)&ws[kk][j4 * 4] = W4[(c0 + kk) * (DD / 4) + j4];
        }
        __syncthreads();

#pragma unroll 8
        for (int kk = 0; kk < KC; kk++) {
            float4 xv = *(const float4*)&xs[kk][ty * 4];
            float4 wv = *(const float4*)&ws[kk][tx * 4];
            float xr[4] = {xv.x, xv.y, xv.z, xv.w};
            float wc[4] = {wv.x, wv.y, wv.z, wv.w};
#pragma unroll
            for (int r = 0; r < 4; r++)
#pragma unroll
                for (int c = 0; c < 4; c++)
                    acc[r][c] = fmaf(xr[r], wc[c], acc[r][c]);
        }
    }

#pragma unroll
    for (int r = 0; r < 4; r++) {
        int gr = r0 + ty * 4 + r;
        if (gr < n) {
            __half2 h01 = __floats2half2_rn(acc[r][0], acc[r][1]);
            __half2 h23 = __floats2half2_rn(acc[r][2], acc[r][3]);
            uint2 pk;
            pk.x = *reinterpret_cast<unsigned*>(&h01);
            pk.y = *reinterpret_cast<unsigned*>(&h23);
            *reinterpret_cast<uint2*>(&g_msg[gr * DD + tx * 4]) = pk;
        }
    }
}

// ---------------------------------------------------------------------------
// K4b: in-place scale (after fork-join): g_msg[i,:] *= dis[i]  (fp32 math)
// Row = 128 halves = 256 bytes = 32 uint2  ->  node = idx >> 5.
// ---------------------------------------------------------------------------
__global__ __launch_bounds__(256) void k_scale(int n) {
    int idx = blockIdx.x * blockDim.x + threadIdx.x;   // over n*32 uint2
    if (idx >= n * 32) return;
    int node = idx >> 5;                                // 32 uint2 per row
    float s = g_dis[node];
    uint2 v = reinterpret_cast<uint2*>(g_msg)[idx];
    __half2 a = *reinterpret_cast<__half2*>(&v.x);
    __half2 b = *reinterpret_cast<__half2*>(&v.y);
    float2 fa = __half22float2(a);
    float2 fb = __half22float2(b);
    a = __floats2half2_rn(fa.x * s, fa.y * s);
    b = __floats2half2_rn(fb.x * s, fb.y * s);
    v.x = *reinterpret_cast<unsigned*>(&a);
    v.y = *reinterpret_cast<unsigned*>(&b);
    reinterpret_cast<uint2*>(g_msg)[idx] = v;
}

// ---------------------------------------------------------------------------
// K5: gather-reduce + finalize (round-2 pure-add structure, fp16 gathers).
// out[i,:] = dis[i] * (sum_{e: col=i} msg[srow[e],:] + msg[i,:]) + bias
// ---------------------------------------------------------------------------
__device__ __forceinline__ float4 h4_to_f4(uint2 v) {
    __half2 h0 = *reinterpret_cast<__half2*>(&v.x);
    __half2 h1 = *reinterpret_cast<__half2*>(&v.y);
    float2 a = __half22float2(h0);
    float2 b = __half22float2(h1);
    return make_float4(a.x, a.y, b.x, b.y);
}

#define NODE_BLOCKS ((NN + 7) / 8)
#define ZERO_BLOCKS 8
__global__ __launch_bounds__(256) void k_reduce(float* __restrict__ out,
                                                const float* __restrict__ bias,
                                                int n) {
    if (blockIdx.x >= NODE_BLOCKS) {
        int t = (blockIdx.x - NODE_BLOCKS) * 256 + threadIdx.x;
        int stride = ZERO_BLOCKS * 256;
        for (int i = t; i < NN; i += stride) {
            g_degcnt[i] = 0;
            g_colcnt[i] = 0;
        }
        return;
    }

    const int node = blockIdx.x * 8 + (threadIdx.x >> 5);
    const int lane = threadIdx.x & 31;
    if (node >= n) return;

    const uint2* m2 = (const uint2*)g_msg;   // row stride = 32 uint2
    const int beg = g_off[node];
    const int end = g_off[node + 1];

    float4 acc = h4_to_f4(m2[node * 32 + lane]);   // self-loop term (pre-scaled)
    int e = beg;
    for (; e + 4 <= end; e += 4) {
        int r0 = g_srow[e + 0];
        int r1 = g_srow[e + 1];
        int r2 = g_srow[e + 2];
        int r3 = g_srow[e + 3];
        float4 v0 = h4_to_f4(m2[r0 * 32 + lane]);
        float4 v1 = h4_to_f4(m2[r1 * 32 + lane]);
        float4 v2 = h4_to_f4(m2[r2 * 32 + lane]);
        float4 v3 = h4_to_f4(m2[r3 * 32 + lane]);
        acc.x += (v0.x + v1.x) + (v2.x + v3.x);
        acc.y += (v0.y + v1.y) + (v2.y + v3.y);
        acc.z += (v0.z + v1.z) + (v2.z + v3.z);
        acc.w += (v0.w + v1.w) + (v2.w + v3.w);
    }
    for (; e < end; e++) {
        float4 v = h4_to_f4(m2[g_srow[e] * 32 + lane]);
        acc.x += v.x; acc.y += v.y; acc.z += v.z; acc.w += v.w;
    }

    const float s = g_dis[node];
    const float4 b = ((const float4*)bias)[lane];
    float4 o;
    o.x = fmaf(s, acc.x, b.x);
    o.y = fmaf(s, acc.y, b.y);
    o.z = fmaf(s, acc.z, b.z);
    o.w = fmaf(s, acc.w, b.w);
    ((float4*)out)[node * 32 + lane] = o;
}

// ---------------------------------------------------------------------------
// Launch: fork GEMM to a side stream; join; scale; reduce.
// ---------------------------------------------------------------------------
extern "C" void kernel_launch(void* const* d_in, const int* in_sizes, int n_in,
                              void* d_out, int out_size) {
    const float* x    = (const float*)d_in[0];
    const int*   ei   = (const int*)d_in[1];
    const float* W    = (const float*)d_in[2];
    const float* bias = (const float*)d_in[3];
    float* out = (float*)d_out;

    const int n = in_sizes[0] / DD;   // 10000
    const int e = in_sizes[1] / 2;    // 640000
    const int half = (e + 1) / 2;

    const int* row = ei;              // edge_index[0]
    const int* col = ei + e;          // edge_index[1]

    cudaStream_t s1;
    cudaEvent_t evFork, evJoin;
    cudaStreamCreateWithFlags(&s1, cudaStreamNonBlocking);
    cudaEventCreateWithFlags(&evFork, cudaEventDisableTiming);
    cudaEventCreateWithFlags(&evJoin, cudaEventDisableTiming);

    // fork: gemm on s1, CSR chain on the main (capture) stream
    cudaEventRecord(evFork, 0);
    cudaStreamWaitEvent(s1, evFork, 0);
    k_gemm<<<(n + TM - 1) / TM, 256, 0, s1>>>(x, W, n);
    cudaEventRecord(evJoin, s1);

    k_hist<<<(half + 255) / 256, 256>>>(row, col, e, half);
    k_scan<<<1, 1024>>>(n);
    k_sort<<<(half + 255) / 256, 256>>>(row, col, e, half);

    // join: scale needs g_msg (s1) and g_dis (main stream)
    cudaStreamWaitEvent(0, evJoin, 0);
    k_scale<<<(n * 32 + 255) / 256, 256>>>(n);
    k_reduce<<<NODE_BLOCKS + ZERO_BLOCKS, 256>>>(out, bias, n);
}